// round 1
// baseline (speedup 1.0000x reference)
#include <cuda_runtime.h>
#include <cuda_bf16.h>

// Problem constants
#define BB   128          // batch
#define LL   192          // seq len
#define DIM  512
#define HID  2048
#define MTOT (BB * LL)    // 24576 tokens

// ---------------------------------------------------------------------------
// Scratch (device globals; no dynamic allocation allowed)
// ---------------------------------------------------------------------------
__device__ float g_emb[(size_t)MTOT * DIM];   // 50.3 MB  (L,B,DIM) layout, token t = l*B + b
__device__ float g_x  [(size_t)MTOT * DIM];   // 50.3 MB
__device__ float g_h  [(size_t)MTOT * HID];   // 201 MB
__device__ float g_msg[(size_t)MTOT * DIM];   // 50.3 MB

// ---------------------------------------------------------------------------
// Embedding gather: emb[t,d] = E_elem[e] + pe[l] + E_aroma[a] + E_charge[c+6] + E_seg[s]
// grid = MTOT blocks, 256 threads, 2 floats/thread
// ---------------------------------------------------------------------------
__global__ void embed_kernel(const int* __restrict__ element,
                             const int* __restrict__ aroma,
                             const int* __restrict__ charge,
                             const int* __restrict__ segment,
                             const float* __restrict__ pe,
                             const float* __restrict__ E_elem,
                             const float* __restrict__ E_charge,
                             const float* __restrict__ E_aroma,
                             const float* __restrict__ E_seg)
{
    int t = blockIdx.x;            // t = l*B + b
    int l = t >> 7;                // B = 128
    int b = t & 127;
    int bl = b * LL + l;           // (B, L) index

    int e  = element[bl];
    int ar = aroma[bl];
    int ch = charge[bl] + 6;
    int sg = segment[bl];

    int d = threadIdx.x * 2;
    float2 v  = *(const float2*)&E_elem  [(size_t)e  * DIM + d];
    float2 p  = *(const float2*)&pe      [(size_t)l  * DIM + d];
    float2 a2 = *(const float2*)&E_aroma [(size_t)ar * DIM + d];
    float2 c2 = *(const float2*)&E_charge[(size_t)ch * DIM + d];
    float2 s2 = *(const float2*)&E_seg   [(size_t)sg * DIM + d];
    float2 o;
    o.x = v.x + p.x + a2.x + c2.x + s2.x;
    o.y = v.y + p.y + a2.y + c2.y + s2.y;
    *(float2*)&g_emb[(size_t)t * DIM + d] = o;
}

// ---------------------------------------------------------------------------
// fp32 tiled GEMM:  C[M,N] = epilogue(A[M,K] @ W[K,N] + bias[N] [+ R[M,N]])
// BM=BN=128, BK=16, 256 threads, 8x8 per-thread microtile.
// All dims are multiples of the tile sizes here, so no bounds checks.
// EPI: 0 = bias, 1 = bias + relu, 2 = bias + residual
// ---------------------------------------------------------------------------
template<int EPI>
__global__ __launch_bounds__(256, 2)
void gemm_kernel(const float* __restrict__ A, const float* __restrict__ W,
                 const float* __restrict__ bias, const float* __restrict__ R,
                 float* __restrict__ C, int N, int K)
{
    __shared__ float As[16][128];  // [k][m]
    __shared__ float Bs[16][128];  // [k][n]

    const int m0 = blockIdx.y * 128;
    const int n0 = blockIdx.x * 128;
    const int tid = threadIdx.x;
    const int mo = (tid >> 4) << 3;   // row offset within tile (0..120)
    const int no = (tid & 15) << 3;   // col offset within tile

    const float* Aptr = A + (size_t)m0 * K;
    const float* Wptr = W + n0;

    float acc[8][8];
#pragma unroll
    for (int i = 0; i < 8; i++)
#pragma unroll
        for (int j = 0; j < 8; j++) acc[i][j] = 0.f;

    for (int k0 = 0; k0 < K; k0 += 16) {
        // A tile: 128 rows x 16 cols = 512 float4 loads, transposed into As[k][m]
#pragma unroll
        for (int i = 0; i < 2; i++) {
            int id  = tid + i * 256;
            int row = id >> 2;            // 0..127
            int c   = (id & 3) << 2;      // 0,4,8,12
            float4 v = *(const float4*)&Aptr[(size_t)row * K + k0 + c];
            As[c + 0][row] = v.x;
            As[c + 1][row] = v.y;
            As[c + 2][row] = v.z;
            As[c + 3][row] = v.w;
        }
        // B tile: 16 rows x 128 cols, straight float4 copy
#pragma unroll
        for (int i = 0; i < 2; i++) {
            int id  = tid + i * 256;
            int row = id >> 5;            // 0..15
            int c   = (id & 31) << 2;     // 0..124
            *(float4*)&Bs[row][c] = *(const float4*)&Wptr[(size_t)(k0 + row) * N + c];
        }
        __syncthreads();

#pragma unroll
        for (int k = 0; k < 16; k++) {
            float a[8], bv[8];
            *(float4*)&a[0]  = *(const float4*)&As[k][mo];
            *(float4*)&a[4]  = *(const float4*)&As[k][mo + 4];
            *(float4*)&bv[0] = *(const float4*)&Bs[k][no];
            *(float4*)&bv[4] = *(const float4*)&Bs[k][no + 4];
#pragma unroll
            for (int i = 0; i < 8; i++)
#pragma unroll
                for (int j = 0; j < 8; j++)
                    acc[i][j] = fmaf(a[i], bv[j], acc[i][j]);
        }
        __syncthreads();
    }

    // Epilogue
    float bv[8];
    *(float4*)&bv[0] = *(const float4*)&bias[n0 + no];
    *(float4*)&bv[4] = *(const float4*)&bias[n0 + no + 4];

#pragma unroll
    for (int i = 0; i < 8; i++) {
        size_t off = (size_t)(m0 + mo + i) * N + n0 + no;
        float out[8];
#pragma unroll
        for (int j = 0; j < 8; j++) {
            float v = acc[i][j] + bv[j];
            if (EPI == 1) v = fmaxf(v, 0.f);
            out[j] = v;
        }
        if (EPI == 2) {
            float4 r0 = *(const float4*)&R[off];
            float4 r1 = *(const float4*)&R[off + 4];
            out[0] += r0.x; out[1] += r0.y; out[2] += r0.z; out[3] += r0.w;
            out[4] += r1.x; out[5] += r1.y; out[6] += r1.z; out[7] += r1.w;
        }
        *(float4*)&C[off]     = *(float4*)&out[0];
        *(float4*)&C[off + 4] = *(float4*)&out[4];
    }
}

// ---------------------------------------------------------------------------
// Bond aggregation:
// out[l,b,:] = emb[l,b,:] + sum_m [bond[b,l,m] != l] * msg[bond[b,l,m], b, :]
// grid = MTOT blocks (one token), 256 threads, 2 floats/thread
// ---------------------------------------------------------------------------
__global__ void agg_kernel(const int* __restrict__ bond,
                           float* __restrict__ out)
{
    int t = blockIdx.x;
    int l = t >> 7;
    int b = t & 127;

    __shared__ int nb[6];
    if (threadIdx.x < 6) {
        int j = bond[((size_t)b * LL + l) * 6 + threadIdx.x];
        nb[threadIdx.x] = (j != l) ? j : -1;
    }
    __syncthreads();

    int d = threadIdx.x * 2;
    float2 acc = *(const float2*)&g_emb[(size_t)t * DIM + d];
#pragma unroll
    for (int m = 0; m < 6; m++) {
        int j = nb[m];
        if (j >= 0) {
            float2 g = *(const float2*)&g_msg[((size_t)j * BB + b) * DIM + d];
            acc.x += g.x;
            acc.y += g.y;
        }
    }
    *(float2*)&out[(size_t)t * DIM + d] = acc;
}

// ---------------------------------------------------------------------------
// Launch
// ---------------------------------------------------------------------------
extern "C" void kernel_launch(void* const* d_in, const int* in_sizes, int n_in,
                              void* d_out, int out_size)
{
    const int*   element  = (const int*)d_in[0];
    const int*   bond     = (const int*)d_in[1];
    const int*   aroma    = (const int*)d_in[2];
    const int*   charge   = (const int*)d_in[3];
    const int*   segment  = (const int*)d_in[4];
    const float* pe       = (const float*)d_in[5];
    const float* E_elem   = (const float*)d_in[6];
    const float* E_charge = (const float*)d_in[7];
    const float* E_aroma  = (const float*)d_in[8];
    const float* E_seg    = (const float*)d_in[9];
    const float* W1 = (const float*)d_in[10];
    const float* b1 = (const float*)d_in[11];
    const float* W2 = (const float*)d_in[12];
    const float* b2 = (const float*)d_in[13];
    const float* W3 = (const float*)d_in[14];
    const float* b3 = (const float*)d_in[15];
    const float* W4 = (const float*)d_in[16];
    const float* b4 = (const float*)d_in[17];
    const float* W5 = (const float*)d_in[18];
    const float* b5 = (const float*)d_in[19];
    float* out = (float*)d_out;

    float *emb, *x, *h, *msg;
    cudaGetSymbolAddress((void**)&emb, g_emb);
    cudaGetSymbolAddress((void**)&x,   g_x);
    cudaGetSymbolAddress((void**)&h,   g_h);
    cudaGetSymbolAddress((void**)&msg, g_msg);

    // 1. Embedding gather -> emb (L,B,DIM)
    embed_kernel<<<MTOT, 256>>>(element, aroma, charge, segment, pe,
                                E_elem, E_charge, E_aroma, E_seg);

    // 2. h = relu(emb @ W1 + b1)      [24576 x 2048]
    gemm_kernel<1><<<dim3(HID / 128, MTOT / 128), 256>>>(emb, W1, b1, nullptr, h, HID, DIM);
    // 3. x = emb + h @ W2 + b2        [24576 x 512]
    gemm_kernel<2><<<dim3(DIM / 128, MTOT / 128), 256>>>(h, W2, b2, emb, x, DIM, HID);
    // 4. h = relu(x @ W3 + b3)
    gemm_kernel<1><<<dim3(HID / 128, MTOT / 128), 256>>>(x, W3, b3, nullptr, h, HID, DIM);
    // 5. x = x + h @ W4 + b4          (in-place residual, per-element safe)
    gemm_kernel<2><<<dim3(DIM / 128, MTOT / 128), 256>>>(h, W4, b4, x, x, DIM, HID);
    // 6. msg = x @ W5 + b5
    gemm_kernel<0><<<dim3(DIM / 128, MTOT / 128), 256>>>(x, W5, b5, nullptr, msg, DIM, DIM);

    // 7. out = emb + masked bond-neighbor sum of msg
    agg_kernel<<<MTOT, 256>>>(bond, out);
}

// round 3
// speedup vs baseline: 1.6125x; 1.6125x over previous
#include <cuda_runtime.h>
#include <cuda_bf16.h>

// Problem constants
#define BB   128          // batch
#define LL   192          // seq len
#define DIM  512
#define HID  2048
#define MTOT (BB * LL)    // 24576 tokens

// ---------------------------------------------------------------------------
// Scratch (device globals; no dynamic allocation allowed)
// ---------------------------------------------------------------------------
__device__ float g_emb[(size_t)MTOT * DIM];   // 50.3 MB  (L,B,DIM) layout, token t = l*B + b
__device__ float g_x  [(size_t)MTOT * DIM];   // 50.3 MB
__device__ float g_h  [(size_t)MTOT * HID];   // 201 MB
__device__ float g_msg[(size_t)MTOT * DIM];   // 50.3 MB

// ---------------------------------------------------------------------------
// Embedding gather: emb[t,d] = E_elem[e] + pe[l] + E_aroma[a] + E_charge[c+6] + E_seg[s]
// grid = MTOT blocks, 256 threads, 2 floats/thread
// ---------------------------------------------------------------------------
__global__ void embed_kernel(const int* __restrict__ element,
                             const int* __restrict__ aroma,
                             const int* __restrict__ charge,
                             const int* __restrict__ segment,
                             const float* __restrict__ pe,
                             const float* __restrict__ E_elem,
                             const float* __restrict__ E_charge,
                             const float* __restrict__ E_aroma,
                             const float* __restrict__ E_seg)
{
    int t = blockIdx.x;            // t = l*B + b
    int l = t >> 7;                // B = 128
    int b = t & 127;
    int bl = b * LL + l;           // (B, L) index

    int e  = element[bl];
    int ar = aroma[bl];
    int ch = charge[bl] + 6;
    int sg = segment[bl];

    int d = threadIdx.x * 2;
    float2 v  = *(const float2*)&E_elem  [(size_t)e  * DIM + d];
    float2 p  = *(const float2*)&pe      [(size_t)l  * DIM + d];
    float2 a2 = *(const float2*)&E_aroma [(size_t)ar * DIM + d];
    float2 c2 = *(const float2*)&E_charge[(size_t)ch * DIM + d];
    float2 s2 = *(const float2*)&E_seg   [(size_t)sg * DIM + d];
    float2 o;
    o.x = v.x + p.x + a2.x + c2.x + s2.x;
    o.y = v.y + p.y + a2.y + c2.y + s2.y;
    *(float2*)&g_emb[(size_t)t * DIM + d] = o;
}

// ---------------------------------------------------------------------------
// fp32 tiled GEMM:  C[M,N] = epilogue(A[M,K] @ W[K,N] + bias[N] [+ R[M,N]])
// BM=BN=128, BK=16, 256 threads, 8x8 per-thread microtile.
// All dims are multiples of the tile sizes here, so no bounds checks.
// EPI: 0 = bias, 1 = bias + relu, 2 = bias + residual
// ---------------------------------------------------------------------------
template<int EPI>
__global__ __launch_bounds__(256, 2)
void gemm_kernel(const float* __restrict__ A, const float* __restrict__ W,
                 const float* __restrict__ bias, const float* __restrict__ R,
                 float* __restrict__ C, int N, int K)
{
    __shared__ float As[16][128];  // [k][m]
    __shared__ float Bs[16][128];  // [k][n]

    const int m0 = blockIdx.y * 128;
    const int n0 = blockIdx.x * 128;
    const int tid = threadIdx.x;
    const int mo = (tid >> 4) << 3;   // row offset within tile (0..120)
    const int no = (tid & 15) << 3;   // col offset within tile

    const float* Aptr = A + (size_t)m0 * K;
    const float* Wptr = W + n0;

    float acc[8][8];
#pragma unroll
    for (int i = 0; i < 8; i++)
#pragma unroll
        for (int j = 0; j < 8; j++) acc[i][j] = 0.f;

    for (int k0 = 0; k0 < K; k0 += 16) {
        // A tile: 128 rows x 16 cols = 512 float4 loads, transposed into As[k][m]
#pragma unroll
        for (int i = 0; i < 2; i++) {
            int id  = tid + i * 256;
            int row = id >> 2;            // 0..127
            int c   = (id & 3) << 2;      // 0,4,8,12
            float4 v = *(const float4*)&Aptr[(size_t)row * K + k0 + c];
            As[c + 0][row] = v.x;
            As[c + 1][row] = v.y;
            As[c + 2][row] = v.z;
            As[c + 3][row] = v.w;
        }
        // B tile: 16 rows x 128 cols, straight float4 copy
#pragma unroll
        for (int i = 0; i < 2; i++) {
            int id  = tid + i * 256;
            int row = id >> 5;            // 0..15
            int c   = (id & 31) << 2;     // 0..124
            *(float4*)&Bs[row][c] = *(const float4*)&Wptr[(size_t)(k0 + row) * N + c];
        }
        __syncthreads();

#pragma unroll
        for (int k = 0; k < 16; k++) {
            float a[8], bv[8];
            *(float4*)&a[0]  = *(const float4*)&As[k][mo];
            *(float4*)&a[4]  = *(const float4*)&As[k][mo + 4];
            *(float4*)&bv[0] = *(const float4*)&Bs[k][no];
            *(float4*)&bv[4] = *(const float4*)&Bs[k][no + 4];
#pragma unroll
            for (int i = 0; i < 8; i++)
#pragma unroll
                for (int j = 0; j < 8; j++)
                    acc[i][j] = fmaf(a[i], bv[j], acc[i][j]);
        }
        __syncthreads();
    }

    // Epilogue
    float bv[8];
    *(float4*)&bv[0] = *(const float4*)&bias[n0 + no];
    *(float4*)&bv[4] = *(const float4*)&bias[n0 + no + 4];

#pragma unroll
    for (int i = 0; i < 8; i++) {
        size_t off = (size_t)(m0 + mo + i) * N + n0 + no;
        float out[8];
#pragma unroll
        for (int j = 0; j < 8; j++) {
            float v = acc[i][j] + bv[j];
            if (EPI == 1) v = fmaxf(v, 0.f);
            out[j] = v;
        }
        if (EPI == 2) {
            float4 r0 = *(const float4*)&R[off];
            float4 r1 = *(const float4*)&R[off + 4];
            out[0] += r0.x; out[1] += r0.y; out[2] += r0.z; out[3] += r0.w;
            out[4] += r1.x; out[5] += r1.y; out[6] += r1.z; out[7] += r1.w;
        }
        *(float4*)&C[off]     = *(float4*)&out[0];
        *(float4*)&C[off + 4] = *(float4*)&out[4];
    }
}

// ---------------------------------------------------------------------------
// Bond aggregation:
// out[l,b,:] = emb[l,b,:] + sum_m [bond[b,l,m] != l] * msg[bond[b,l,m], b, :]
// grid = MTOT blocks (one token), 256 threads, 2 floats/thread
// ---------------------------------------------------------------------------
__global__ void agg_kernel(const int* __restrict__ bond,
                           float* __restrict__ out)
{
    int t = blockIdx.x;
    int l = t >> 7;
    int b = t & 127;

    __shared__ int nb[6];
    if (threadIdx.x < 6) {
        int j = bond[((size_t)b * LL + l) * 6 + threadIdx.x];
        nb[threadIdx.x] = (j != l) ? j : -1;
    }
    __syncthreads();

    int d = threadIdx.x * 2;
    float2 acc = *(const float2*)&g_emb[(size_t)t * DIM + d];
#pragma unroll
    for (int m = 0; m < 6; m++) {
        int j = nb[m];
        if (j >= 0) {
            float2 g = *(const float2*)&g_msg[((size_t)j * BB + b) * DIM + d];
            acc.x += g.x;
            acc.y += g.y;
        }
    }
    *(float2*)&out[(size_t)t * DIM + d] = acc;
}

// ---------------------------------------------------------------------------
// Launch
// ---------------------------------------------------------------------------
extern "C" void kernel_launch(void* const* d_in, const int* in_sizes, int n_in,
                              void* d_out, int out_size)
{
    const int*   element  = (const int*)d_in[0];
    const int*   bond     = (const int*)d_in[1];
    const int*   aroma    = (const int*)d_in[2];
    const int*   charge   = (const int*)d_in[3];
    const int*   segment  = (const int*)d_in[4];
    const float* pe       = (const float*)d_in[5];
    const float* E_elem   = (const float*)d_in[6];
    const float* E_charge = (const float*)d_in[7];
    const float* E_aroma  = (const float*)d_in[8];
    const float* E_seg    = (const float*)d_in[9];
    const float* W1 = (const float*)d_in[10];
    const float* b1 = (const float*)d_in[11];
    const float* W2 = (const float*)d_in[12];
    const float* b2 = (const float*)d_in[13];
    const float* W3 = (const float*)d_in[14];
    const float* b3 = (const float*)d_in[15];
    const float* W4 = (const float*)d_in[16];
    const float* b4 = (const float*)d_in[17];
    const float* W5 = (const float*)d_in[18];
    const float* b5 = (const float*)d_in[19];
    float* out = (float*)d_out;

    float *emb, *x, *h, *msg;
    cudaGetSymbolAddress((void**)&emb, g_emb);
    cudaGetSymbolAddress((void**)&x,   g_x);
    cudaGetSymbolAddress((void**)&h,   g_h);
    cudaGetSymbolAddress((void**)&msg, g_msg);

    // 1. Embedding gather -> emb (L,B,DIM)
    embed_kernel<<<MTOT, 256>>>(element, aroma, charge, segment, pe,
                                E_elem, E_charge, E_aroma, E_seg);

    // 2. h = relu(emb @ W1 + b1)      [24576 x 2048]
    gemm_kernel<1><<<dim3(HID / 128, MTOT / 128), 256>>>(emb, W1, b1, nullptr, h, HID, DIM);
    // 3. x = emb + h @ W2 + b2        [24576 x 512]
    gemm_kernel<2><<<dim3(DIM / 128, MTOT / 128), 256>>>(h, W2, b2, emb, x, DIM, HID);
    // 4. h = relu(x @ W3 + b3)
    gemm_kernel<1><<<dim3(HID / 128, MTOT / 128), 256>>>(x, W3, b3, nullptr, h, HID, DIM);
    // 5. x = x + h @ W4 + b4          (in-place residual, per-element safe)
    gemm_kernel<2><<<dim3(DIM / 128, MTOT / 128), 256>>>(h, W4, b4, x, x, DIM, HID);
    // 6. msg = x @ W5 + b5
    gemm_kernel<0><<<dim3(DIM / 128, MTOT / 128), 256>>>(x, W5, b5, nullptr, msg, DIM, DIM);

    // 7. out = emb + masked bond-neighbor sum of msg
    agg_kernel<<<MTOT, 256>>>(bond, out);
}

// round 7
// speedup vs baseline: 4.6637x; 2.8921x over previous
#include <cuda_runtime.h>
#include <cuda_bf16.h>
#include <cstdint>

#define BB   128
#define LL   192
#define DIM  512
#define HID  2048
#define MTOT (BB * LL)    // 24576

// ---------------------------------------------------------------------------
// Scratch (device globals; no dynamic allocation allowed)
// ---------------------------------------------------------------------------
__device__ __align__(256) float g_emb[(size_t)MTOT * DIM];
__device__ __align__(256) float g_x  [(size_t)MTOT * DIM];
__device__ __align__(256) float g_msg[(size_t)MTOT * DIM];
__device__ __align__(256) __nv_bfloat16 g_embh[(size_t)MTOT * DIM];
__device__ __align__(256) __nv_bfloat16 g_embl[(size_t)MTOT * DIM];
__device__ __align__(256) __nv_bfloat16 g_xh[(size_t)MTOT * DIM];
__device__ __align__(256) __nv_bfloat16 g_xl[(size_t)MTOT * DIM];
__device__ __align__(256) __nv_bfloat16 g_hh[(size_t)MTOT * HID];
__device__ __align__(256) __nv_bfloat16 g_hl[(size_t)MTOT * HID];
// transposed bf16 hi/lo weights, layout [N, K] K-contiguous
__device__ __align__(256) __nv_bfloat16 g_w1h[(size_t)HID * DIM];
__device__ __align__(256) __nv_bfloat16 g_w1l[(size_t)HID * DIM];
__device__ __align__(256) __nv_bfloat16 g_w2h[(size_t)DIM * HID];
__device__ __align__(256) __nv_bfloat16 g_w2l[(size_t)DIM * HID];
__device__ __align__(256) __nv_bfloat16 g_w3h[(size_t)HID * DIM];
__device__ __align__(256) __nv_bfloat16 g_w3l[(size_t)HID * DIM];
__device__ __align__(256) __nv_bfloat16 g_w4h[(size_t)DIM * HID];
__device__ __align__(256) __nv_bfloat16 g_w4l[(size_t)DIM * HID];
__device__ __align__(256) __nv_bfloat16 g_w5h[(size_t)DIM * DIM];
__device__ __align__(256) __nv_bfloat16 g_w5l[(size_t)DIM * DIM];

// ---------------------------------------------------------------------------
// Low-level helpers (all baseline sm_80+ instructions; NO 'a'-only features)
// ---------------------------------------------------------------------------
#define SWZ(o) ((o) ^ (((o) >> 3) & 0x70))   // SW128: XOR bits[9:7] into [6:4]

__device__ __forceinline__ void cpasync16(uint32_t dst, const void* src) {
    size_t gp = __cvta_generic_to_global(src);
    asm volatile("cp.async.cg.shared.global [%0], [%1], 16;" :: "r"(dst), "l"(gp) : "memory");
}
#define CP_COMMIT() asm volatile("cp.async.commit_group;" ::: "memory")
#define CP_WAIT(n)  asm volatile("cp.async.wait_group %0;" :: "n"(n) : "memory")

__device__ __forceinline__ void ldsm4(uint32_t r[4], uint32_t addr) {
    asm volatile("ldmatrix.sync.aligned.m8n8.x4.shared.b16 {%0,%1,%2,%3}, [%4];"
        : "=r"(r[0]), "=r"(r[1]), "=r"(r[2]), "=r"(r[3]) : "r"(addr));
}

__device__ __forceinline__ void mma16816(float d[4], const uint32_t a[4],
                                         uint32_t b0, uint32_t b1) {
    asm volatile("mma.sync.aligned.m16n8k16.row.col.f32.bf16.bf16.f32 "
        "{%0,%1,%2,%3}, {%4,%5,%6,%7}, {%8,%9}, {%0,%1,%2,%3};"
        : "+f"(d[0]), "+f"(d[1]), "+f"(d[2]), "+f"(d[3])
        : "r"(a[0]), "r"(a[1]), "r"(a[2]), "r"(a[3]), "r"(b0), "r"(b1));
}

__device__ __forceinline__ uint32_t pack_bf16x2(float x, float y) {
    __nv_bfloat162 h = __halves2bfloat162(__float2bfloat16(x), __float2bfloat16(y));
    return *reinterpret_cast<uint32_t*>(&h);
}

// ---------------------------------------------------------------------------
// GEMM: C[M,N] = epi(Asplit[M,K] @ Bsplit[N,K]^T + bias [+ R])
// CTA tile 128(M) x 256(N), BK = 64.  8 warps, warp tile 64x64 (grid 2m x 4n).
// SMEM stage = A_hi(16K)|A_lo(16K)|B_hi(32K)|B_lo(32K) = 96 KB, double buffered.
// 3-term bf16 split per k16: ah*bh + ah*bl + al*bh (fp32 accumulate).
// ---------------------------------------------------------------------------
static constexpr int STAGE_BYTES = 98304;
static constexpr int SMEM_TOTAL_GEMM = 2 * STAGE_BYTES;   // 192 KB

__device__ __forceinline__ void load_chunk(
    uint32_t stage,
    const __nv_bfloat16* __restrict__ Ah, const __nv_bfloat16* __restrict__ Al,
    const __nv_bfloat16* __restrict__ Bh, const __nv_bfloat16* __restrict__ Bl,
    int m0, int n0, int k0, int K, int tid)
{
#pragma unroll
    for (int j = 0; j < 24; j++) {
        const __nv_bfloat16* src;
        uint32_t dst;
        if (j < 8) {                       // A: 128 rows x 8 chunks, hi then lo
            int s = (j & 3) * 256 + tid;   // 0..1023
            int r = s >> 3;
            int c = s & 7;
            src = (j < 4 ? Ah : Al) + (size_t)(m0 + r) * K + k0 + c * 8;
            dst = stage + (j < 4 ? 0 : 16384) + SWZ(r * 128 + c * 16);
        } else {                           // B: 256 rows x 8 chunks, hi then lo
            int jj = j - 8;
            int s = (jj & 7) * 256 + tid;  // 0..2047
            int r = s >> 3;
            int c = s & 7;
            src = (j < 16 ? Bh : Bl) + (size_t)(n0 + r) * K + k0 + c * 8;
            dst = stage + (j < 16 ? 32768 : 65536) + SWZ(r * 128 + c * 16);
        }
        cpasync16(dst, src);
    }
}

template<int EPI, bool WHILO, bool WF32>   // EPI: 0=bias, 1=bias+relu, 2=bias+residual
__global__ __launch_bounds__(256, 1)
void mma_gemm(const __nv_bfloat16* __restrict__ Ah, const __nv_bfloat16* __restrict__ Al,
              const __nv_bfloat16* __restrict__ Bh, const __nv_bfloat16* __restrict__ Bl,
              const float* __restrict__ bias, const float* __restrict__ R,
              float* __restrict__ Cf,
              __nv_bfloat16* __restrict__ Ch, __nv_bfloat16* __restrict__ Cl,
              int N, int K)
{
    extern __shared__ char smem[];
    uint32_t sb = (uint32_t)__cvta_generic_to_shared(smem);
    const int tid  = threadIdx.x;
    const int wid  = tid >> 5;
    const int lane = tid & 31;
    const int m0 = blockIdx.y * 128, n0 = blockIdx.x * 256;
    const int wm = wid & 1;        // 0..1 (64-row slab)
    const int wn = wid >> 1;       // 0..3 (64-col slab)

    float acc[4][8][4];
#pragma unroll
    for (int mt = 0; mt < 4; mt++)
#pragma unroll
        for (int nt = 0; nt < 8; nt++)
#pragma unroll
            for (int q = 0; q < 4; q++) acc[mt][nt][q] = 0.f;

    // per-lane ldmatrix row geometry
    // A (m16k16, x4 mats: [m0-7,k0-7][m8-15,k0-7][m0-7,k8-15][m8-15,k8-15])
    const int rA  = wm * 64 + ((lane >> 3) & 1) * 8 + (lane & 7);
    const int qkA = (lane >> 4) & 1;                    // k-chunk select within k16
    // B (two n8k16 tiles per x4: [n0,k0][n0,k8][n1,k0][n1,k8])
    const int rB  = wn * 64 + ((lane >> 4) & 1) * 8 + (lane & 7);
    const int kcB = (lane >> 3) & 1;
    const int rx  = lane & 7;                           // swizzle phase (rows mod 8)

    const int C = K >> 6;
    load_chunk(sb,               Ah, Al, Bh, Bl, m0, n0, 0,  K, tid); CP_COMMIT();
    load_chunk(sb + STAGE_BYTES, Ah, Al, Bh, Bl, m0, n0, 64, K, tid); CP_COMMIT();

    for (int i = 0; i < C; i++) {
        uint32_t stage = sb + (i & 1) * STAGE_BYTES;
        if (i + 1 < C) { CP_WAIT(1); } else { CP_WAIT(0); }
        __syncthreads();

        const uint32_t aH = stage, aL = stage + 16384;
        const uint32_t bH = stage + 32768, bL = stage + 65536;

#pragma unroll
        for (int ks = 0; ks < 4; ks++) {
            uint32_t ah[4][4], al[4][4], bh[4][4], bl[4][4];
#pragma unroll
            for (int mt = 0; mt < 4; mt++) {
                uint32_t off = (uint32_t)(rA + mt * 16) * 128
                             + (uint32_t)(((ks * 2 + qkA) ^ rx) * 16);
                ldsm4(ah[mt], aH + off);
                ldsm4(al[mt], aL + off);
            }
#pragma unroll
            for (int p = 0; p < 4; p++) {
                uint32_t off = (uint32_t)(rB + p * 16) * 128
                             + (uint32_t)(((ks * 2 + kcB) ^ rx) * 16);
                ldsm4(bh[p], bH + off);
                ldsm4(bl[p], bL + off);
            }
#pragma unroll
            for (int mt = 0; mt < 4; mt++)
#pragma unroll
                for (int nt = 0; nt < 8; nt++) {
                    int p = nt >> 1, h = (nt & 1) * 2;
                    mma16816(acc[mt][nt], ah[mt], bh[p][h], bh[p][h + 1]);
                    mma16816(acc[mt][nt], ah[mt], bl[p][h], bl[p][h + 1]);
                    mma16816(acc[mt][nt], al[mt], bh[p][h], bh[p][h + 1]);
                }
        }
        __syncthreads();
        if (i + 2 < C) {
            load_chunk(stage, Ah, Al, Bh, Bl, m0, n0, (i + 2) * 64, K, tid);
            CP_COMMIT();
        }
    }

    // -------- epilogue (registers -> global), fused bias/relu/residual/split
    const int mbase = m0 + wm * 64;
    const int nbase = n0 + wn * 64;
#pragma unroll
    for (int mt = 0; mt < 4; mt++) {
        const int r0 = mbase + mt * 16 + (lane >> 2);
        const int r1 = r0 + 8;
#pragma unroll
        for (int nt = 0; nt < 8; nt++) {
            const int c = nbase + nt * 8 + (lane & 3) * 2;
            float2 bq = *(const float2*)&bias[c];
            float v00 = acc[mt][nt][0] + bq.x, v01 = acc[mt][nt][1] + bq.y;
            float v10 = acc[mt][nt][2] + bq.x, v11 = acc[mt][nt][3] + bq.y;
            if constexpr (EPI == 1) {
                v00 = fmaxf(v00, 0.f); v01 = fmaxf(v01, 0.f);
                v10 = fmaxf(v10, 0.f); v11 = fmaxf(v11, 0.f);
            }
            if constexpr (EPI == 2) {
                float2 q0 = *(const float2*)&R[(size_t)r0 * N + c];
                float2 q1 = *(const float2*)&R[(size_t)r1 * N + c];
                v00 += q0.x; v01 += q0.y; v10 += q1.x; v11 += q1.y;
            }
            if constexpr (WF32) {
                *(float2*)&Cf[(size_t)r0 * N + c] = make_float2(v00, v01);
                *(float2*)&Cf[(size_t)r1 * N + c] = make_float2(v10, v11);
            }
            if constexpr (WHILO) {
                uint32_t h0 = pack_bf16x2(v00, v01);
                uint32_t h1 = pack_bf16x2(v10, v11);
                float h00 = __bfloat162float(__float2bfloat16(v00));
                float h01 = __bfloat162float(__float2bfloat16(v01));
                float h10 = __bfloat162float(__float2bfloat16(v10));
                float h11 = __bfloat162float(__float2bfloat16(v11));
                uint32_t l0 = pack_bf16x2(v00 - h00, v01 - h01);
                uint32_t l1 = pack_bf16x2(v10 - h10, v11 - h11);
                *(uint32_t*)&Ch[(size_t)r0 * N + c] = h0;
                *(uint32_t*)&Ch[(size_t)r1 * N + c] = h1;
                *(uint32_t*)&Cl[(size_t)r0 * N + c] = l0;
                *(uint32_t*)&Cl[(size_t)r1 * N + c] = l1;
            }
        }
    }
}

// ---------------------------------------------------------------------------
// Weight prep: W[K,N] fp32 -> Wt_hi/Wt_lo [N,K] bf16 (tiled transpose + split)
// ---------------------------------------------------------------------------
__global__ void wprep_kernel(const float* __restrict__ W,
                             __nv_bfloat16* __restrict__ Th,
                             __nv_bfloat16* __restrict__ Tl, int K, int N)
{
    __shared__ float t[32][33];
    int n0 = blockIdx.x * 32, k0 = blockIdx.y * 32;
    int tx = threadIdx.x, ty = threadIdx.y;
#pragma unroll
    for (int i = 0; i < 32; i += 8)
        t[ty + i][tx] = W[(size_t)(k0 + ty + i) * N + n0 + tx];
    __syncthreads();
#pragma unroll
    for (int i = 0; i < 32; i += 8) {
        float v = t[tx][ty + i];
        size_t o = (size_t)(n0 + ty + i) * K + k0 + tx;
        __nv_bfloat16 h = __float2bfloat16(v);
        Th[o] = h;
        Tl[o] = __float2bfloat16(v - __bfloat162float(h));
    }
}

// ---------------------------------------------------------------------------
// Embedding gather -> emb fp32 + hi/lo bf16.  (L,B,DIM) layout, t = l*B + b
// ---------------------------------------------------------------------------
__global__ void embed_kernel(const int* __restrict__ element,
                             const int* __restrict__ aroma,
                             const int* __restrict__ charge,
                             const int* __restrict__ segment,
                             const float* __restrict__ pe,
                             const float* __restrict__ E_elem,
                             const float* __restrict__ E_charge,
                             const float* __restrict__ E_aroma,
                             const float* __restrict__ E_seg)
{
    int t = blockIdx.x;
    int l = t >> 7;
    int b = t & 127;
    int bl = b * LL + l;

    int e  = element[bl];
    int ar = aroma[bl];
    int ch = charge[bl] + 6;
    int sg = segment[bl];

    int d = threadIdx.x * 2;
    float2 v  = *(const float2*)&E_elem  [(size_t)e  * DIM + d];
    float2 p  = *(const float2*)&pe      [(size_t)l  * DIM + d];
    float2 a2 = *(const float2*)&E_aroma [(size_t)ar * DIM + d];
    float2 c2 = *(const float2*)&E_charge[(size_t)ch * DIM + d];
    float2 s2 = *(const float2*)&E_seg   [(size_t)sg * DIM + d];
    float ox = v.x + p.x + a2.x + c2.x + s2.x;
    float oy = v.y + p.y + a2.y + c2.y + s2.y;
    size_t o = (size_t)t * DIM + d;
    *(float2*)&g_emb[o] = make_float2(ox, oy);

    float hx = __bfloat162float(__float2bfloat16(ox));
    float hy = __bfloat162float(__float2bfloat16(oy));
    *(uint32_t*)&g_embh[o] = pack_bf16x2(ox, oy);
    *(uint32_t*)&g_embl[o] = pack_bf16x2(ox - hx, oy - hy);
}

// ---------------------------------------------------------------------------
// Bond aggregation: out[l,b,:] = emb[l,b,:] + sum_m [bond!=l] msg[bond, b, :]
// ---------------------------------------------------------------------------
__global__ void agg_kernel(const int* __restrict__ bond,
                           float* __restrict__ out)
{
    int t = blockIdx.x;
    int l = t >> 7;
    int b = t & 127;

    __shared__ int nb[6];
    if (threadIdx.x < 6) {
        int j = bond[((size_t)b * LL + l) * 6 + threadIdx.x];
        nb[threadIdx.x] = (j != l) ? j : -1;
    }
    __syncthreads();

    int d = threadIdx.x * 2;
    float2 acc = *(const float2*)&g_emb[(size_t)t * DIM + d];
#pragma unroll
    for (int m = 0; m < 6; m++) {
        int j = nb[m];
        if (j >= 0) {
            float2 g = *(const float2*)&g_msg[((size_t)j * BB + b) * DIM + d];
            acc.x += g.x;
            acc.y += g.y;
        }
    }
    *(float2*)&out[(size_t)t * DIM + d] = acc;
}

// ---------------------------------------------------------------------------
// Launch
// ---------------------------------------------------------------------------
extern "C" void kernel_launch(void* const* d_in, const int* in_sizes, int n_in,
                              void* d_out, int out_size)
{
    const int*   element  = (const int*)d_in[0];
    const int*   bond     = (const int*)d_in[1];
    const int*   aroma    = (const int*)d_in[2];
    const int*   charge   = (const int*)d_in[3];
    const int*   segment  = (const int*)d_in[4];
    const float* pe       = (const float*)d_in[5];
    const float* E_elem   = (const float*)d_in[6];
    const float* E_charge = (const float*)d_in[7];
    const float* E_aroma  = (const float*)d_in[8];
    const float* E_seg    = (const float*)d_in[9];
    const float* W1 = (const float*)d_in[10];
    const float* b1 = (const float*)d_in[11];
    const float* W2 = (const float*)d_in[12];
    const float* b2 = (const float*)d_in[13];
    const float* W3 = (const float*)d_in[14];
    const float* b3 = (const float*)d_in[15];
    const float* W4 = (const float*)d_in[16];
    const float* b4 = (const float*)d_in[17];
    const float* W5 = (const float*)d_in[18];
    const float* b5 = (const float*)d_in[19];
    float* out = (float*)d_out;

    cudaFuncSetAttribute(mma_gemm<1, true,  false>, cudaFuncAttributeMaxDynamicSharedMemorySize, SMEM_TOTAL_GEMM);
    cudaFuncSetAttribute(mma_gemm<2, true,  true >, cudaFuncAttributeMaxDynamicSharedMemorySize, SMEM_TOTAL_GEMM);
    cudaFuncSetAttribute(mma_gemm<2, true,  false>, cudaFuncAttributeMaxDynamicSharedMemorySize, SMEM_TOTAL_GEMM);
    cudaFuncSetAttribute(mma_gemm<0, false, true >, cudaFuncAttributeMaxDynamicSharedMemorySize, SMEM_TOTAL_GEMM);

    float *emb, *x, *msg;
    __nv_bfloat16 *embh, *embl, *xh, *xl, *hh, *hl;
    __nv_bfloat16 *w1h, *w1l, *w2h, *w2l, *w3h, *w3l, *w4h, *w4l, *w5h, *w5l;
    cudaGetSymbolAddress((void**)&emb,  g_emb);
    cudaGetSymbolAddress((void**)&x,    g_x);
    cudaGetSymbolAddress((void**)&msg,  g_msg);
    cudaGetSymbolAddress((void**)&embh, g_embh);
    cudaGetSymbolAddress((void**)&embl, g_embl);
    cudaGetSymbolAddress((void**)&xh,   g_xh);
    cudaGetSymbolAddress((void**)&xl,   g_xl);
    cudaGetSymbolAddress((void**)&hh,   g_hh);
    cudaGetSymbolAddress((void**)&hl,   g_hl);
    cudaGetSymbolAddress((void**)&w1h,  g_w1h);
    cudaGetSymbolAddress((void**)&w1l,  g_w1l);
    cudaGetSymbolAddress((void**)&w2h,  g_w2h);
    cudaGetSymbolAddress((void**)&w2l,  g_w2l);
    cudaGetSymbolAddress((void**)&w3h,  g_w3h);
    cudaGetSymbolAddress((void**)&w3l,  g_w3l);
    cudaGetSymbolAddress((void**)&w4h,  g_w4h);
    cudaGetSymbolAddress((void**)&w4l,  g_w4l);
    cudaGetSymbolAddress((void**)&w5h,  g_w5h);
    cudaGetSymbolAddress((void**)&w5l,  g_w5l);

    dim3 wblk(32, 8);

    // 1. embedding gather (fp32 + bf16 hi/lo)
    embed_kernel<<<MTOT, 256>>>(element, aroma, charge, segment, pe,
                                E_elem, E_charge, E_aroma, E_seg);
    // 2. weight transpose+split
    wprep_kernel<<<dim3(HID / 32, DIM / 32), wblk>>>(W1, w1h, w1l, DIM, HID);
    wprep_kernel<<<dim3(DIM / 32, HID / 32), wblk>>>(W2, w2h, w2l, HID, DIM);
    wprep_kernel<<<dim3(HID / 32, DIM / 32), wblk>>>(W3, w3h, w3l, DIM, HID);
    wprep_kernel<<<dim3(DIM / 32, HID / 32), wblk>>>(W4, w4h, w4l, HID, DIM);
    wprep_kernel<<<dim3(DIM / 32, DIM / 32), wblk>>>(W5, w5h, w5l, DIM, DIM);

    // 3. h1 = relu(emb @ W1 + b1)      -> hi/lo
    mma_gemm<1, true, false><<<dim3(HID / 256, MTOT / 128), 256, SMEM_TOTAL_GEMM>>>(
        embh, embl, w1h, w1l, b1, nullptr, nullptr, hh, hl, HID, DIM);
    // 4. x1 = emb + h1 @ W2 + b2       -> fp32 + hi/lo
    mma_gemm<2, true, true><<<dim3(DIM / 256, MTOT / 128), 256, SMEM_TOTAL_GEMM>>>(
        hh, hl, w2h, w2l, b2, emb, x, xh, xl, DIM, HID);
    // 5. h2 = relu(x1 @ W3 + b3)       -> hi/lo
    mma_gemm<1, true, false><<<dim3(HID / 256, MTOT / 128), 256, SMEM_TOTAL_GEMM>>>(
        xh, xl, w3h, w3l, b3, nullptr, nullptr, hh, hl, HID, DIM);
    // 6. x2 = x1 + h2 @ W4 + b4        -> hi/lo only
    mma_gemm<2, true, false><<<dim3(DIM / 256, MTOT / 128), 256, SMEM_TOTAL_GEMM>>>(
        hh, hl, w4h, w4l, b4, x, nullptr, xh, xl, DIM, HID);
    // 7. msg = x2 @ W5 + b5            -> fp32
    mma_gemm<0, false, true><<<dim3(DIM / 256, MTOT / 128), 256, SMEM_TOTAL_GEMM>>>(
        xh, xl, w5h, w5l, b5, nullptr, msg, nullptr, nullptr, DIM, DIM);

    // 8. out = emb + masked bond-neighbor sum of msg
    agg_kernel<<<MTOT, 256>>>(bond, out);
}